// round 2
// baseline (speedup 1.0000x reference)
#include <cuda_runtime.h>
#include <cstdint>

#define NNODES 100000
#define NEDGES 1600000
#define NELEMS 12800000   // NNODES*128

// ---------------- scratch (static device globals: allocation-free) ----------
__device__ float g_bufS[(size_t)NNODES * 128];   // self GEMM out / pre-activation accumulator
__device__ float g_bufG[(size_t)NNODES * 128];   // neigh GEMM out
__device__ float g_bufH[(size_t)NNODES * 128];   // hidden activations
__device__ float g_invdeg[NNODES];
__device__ float g_sum[128];
__device__ float g_sumsq[128];
__device__ float g_scale[128];
__device__ float g_shift[128];

// ---------------- threefry2x32 (exact JAX implementation) -------------------
__host__ __device__ __forceinline__ void tf2x32(uint32_t k0, uint32_t k1,
                                                uint32_t& x0, uint32_t& x1)
{
    const uint32_t ks0 = k0, ks1 = k1, ks2 = k0 ^ k1 ^ 0x1BD11BDAu;
    const uint32_t ks[3] = {ks0, ks1, ks2};
    const int rot0[4] = {13, 15, 26, 6};
    const int rot1[4] = {17, 29, 16, 24};
    x0 += ks0; x1 += ks1;
#pragma unroll
    for (int b = 0; b < 5; b++) {
        const int* r = (b & 1) ? rot1 : rot0;
#pragma unroll
        for (int i = 0; i < 4; i++) {
            x0 += x1;
            x1 = (x1 << r[i]) | (x1 >> (32 - r[i]));
            x1 ^= x0;
        }
        x0 += ks[(b + 1) % 3];
        x1 += ks[(b + 2) % 3] + (uint32_t)(b + 1);
    }
}

// ---------------- degree ----------------------------------------------------
__global__ void k_zero_deg()
{
    int i = blockIdx.x * blockDim.x + threadIdx.x;
    if (i < NNODES) g_invdeg[i] = 0.0f;
}

__global__ void k_count_deg(const int* __restrict__ dst)
{
    int e = blockIdx.x * blockDim.x + threadIdx.x;
    if (e < NEDGES) atomicAdd(&g_invdeg[dst[e]], 1.0f);
}

__global__ void k_finish_deg()
{
    int i = blockIdx.x * blockDim.x + threadIdx.x;
    if (i < NNODES) {
        float d = g_invdeg[i];
        g_invdeg[i] = 1.0f / fmaxf(d, 1.0f);
    }
}

// ---------------- GEMM: out[N,F] = H[N,128] @ W[128,F] (+ bias) -------------
// block = 256 threads, BM = 64 rows, thread tile = RPT rows x 4 cols (float4)
template <int F, int RPT>
__global__ void __launch_bounds__(256)
sage_gemm(const float* __restrict__ H, const float* __restrict__ W,
          const float* __restrict__ bias, float* __restrict__ out)
{
    constexpr int CG = F / 4;        // float4 col groups
    constexpr int TY = 256 / CG;     // row groups
    constexpr int BM = TY * RPT;     // rows per block (64)
    __shared__ float hs[BM][128];

    const int t = threadIdx.x;
    const int row0 = blockIdx.x * BM;

    // stage H tile (BM x 128) into smem, float4, OOB rows -> 0
    for (int i = t; i < BM * 32; i += 256) {
        int r = i >> 5, c = i & 31;
        int gr = row0 + r;
        float4 v = make_float4(0.f, 0.f, 0.f, 0.f);
        if (gr < NNODES) v = __ldg((const float4*)(H + (size_t)gr * 128) + c);
        *((float4*)&hs[r][0] + c) = v;
    }
    __syncthreads();

    const int tx = t % CG, ty = t / CG;
    float acc[RPT][4];
#pragma unroll
    for (int r = 0; r < RPT; r++) { acc[r][0] = acc[r][1] = acc[r][2] = acc[r][3] = 0.f; }

    const float4* Wv = (const float4*)W;
#pragma unroll 4
    for (int k = 0; k < 128; k++) {
        float4 b = __ldg(Wv + k * CG + tx);
#pragma unroll
        for (int r = 0; r < RPT; r++) {
            float a = hs[ty * RPT + r][k];
            acc[r][0] = fmaf(a, b.x, acc[r][0]);
            acc[r][1] = fmaf(a, b.y, acc[r][1]);
            acc[r][2] = fmaf(a, b.z, acc[r][2]);
            acc[r][3] = fmaf(a, b.w, acc[r][3]);
        }
    }

    float4 bb = make_float4(0.f, 0.f, 0.f, 0.f);
    if (bias) bb = __ldg((const float4*)bias + tx);

#pragma unroll
    for (int r = 0; r < RPT; r++) {
        int gr = row0 + ty * RPT + r;
        if (gr < NNODES) {
            float4 o = make_float4(acc[r][0] + bb.x, acc[r][1] + bb.y,
                                   acc[r][2] + bb.z, acc[r][3] + bb.w);
            *((float4*)(out + (size_t)gr * F) + tx) = o;
        }
    }
}

// ---------------- edge aggregation: S[dst] += invdeg[dst] * G[src] ----------
__global__ void k_edge_agg128(const float* __restrict__ G, float* __restrict__ S,
                              const int* __restrict__ src, const int* __restrict__ dst)
{
    long gidx = (long)blockIdx.x * blockDim.x + threadIdx.x;
    int e = (int)(gidx >> 5);
    if (e >= NEDGES) return;
    int lane = threadIdx.x & 31;
    int s = __ldg(&src[e]);
    int d = __ldg(&dst[e]);
    float w = __ldg(&g_invdeg[d]);
    float4 g = __ldg((const float4*)(G + (size_t)s * 128) + lane);
    float* p = S + (size_t)d * 128 + lane * 4;
    asm volatile("red.global.add.v4.f32 [%0], {%1,%2,%3,%4};"
                 :: "l"(p), "f"(g.x * w), "f"(g.y * w), "f"(g.z * w), "f"(g.w * w)
                 : "memory");
}

__global__ void k_edge_agg64(const float* __restrict__ G, float* __restrict__ S,
                             const int* __restrict__ src, const int* __restrict__ dst)
{
    long gidx = (long)blockIdx.x * blockDim.x + threadIdx.x;
    int e = (int)(gidx >> 4);
    if (e >= NEDGES) return;
    int lane = threadIdx.x & 15;
    int s = __ldg(&src[e]);
    int d = __ldg(&dst[e]);
    float w = __ldg(&g_invdeg[d]);
    float4 g = __ldg((const float4*)(G + (size_t)s * 64) + lane);
    float* p = S + (size_t)d * 64 + lane * 4;
    asm volatile("red.global.add.v4.f32 [%0], {%1,%2,%3,%4};"
                 :: "l"(p), "f"(g.x * w), "f"(g.y * w), "f"(g.z * w), "f"(g.w * w)
                 : "memory");
}

// ---------------- batchnorm stats + finalize --------------------------------
__global__ void k_zero_stats()
{
    int t = threadIdx.x;
    if (t < 128) { g_sum[t] = 0.f; g_sumsq[t] = 0.f; }
}

__global__ void k_bn_stats(const float* __restrict__ S)
{
    int f = threadIdx.x & 127;
    int r = blockIdx.x * 2 + (threadIdx.x >> 7);
    int stride = gridDim.x * 2;
    float s = 0.f, q = 0.f;
    for (; r < NNODES; r += stride) {
        float v = S[(size_t)r * 128 + f];
        s += v;
        q = fmaf(v, v, q);
    }
    atomicAdd(&g_sum[f], s);
    atomicAdd(&g_sumsq[f], q);
}

__global__ void k_bn_finalize(const float* __restrict__ gamma, const float* __restrict__ beta)
{
    int f = threadIdx.x;
    float mu = g_sum[f] * (1.0f / NNODES);
    float var = fmaxf(g_sumsq[f] * (1.0f / NNODES) - mu * mu, 0.f);
    float sc = gamma[f] * rsqrtf(var + 1e-5f);
    g_scale[f] = sc;
    g_shift[f] = beta[f] - mu * sc;
}

// ---------------- fused BN * ReLU * dropout ----------------------------------
// JAX partitionable threefry (default since 0.4.36):
//   bits(j) = x0out ^ x1out of threefry2x32(key, (hi,lo)=(0,j))
//   keep iff uniform >= 0.5 iff bit31(bits) == 1
__global__ void k_bn_relu_drop(const float* __restrict__ S, float* __restrict__ out,
                               uint32_t k0, uint32_t k1)
{
    int j = blockIdx.x * blockDim.x + threadIdx.x;
    if (j >= NELEMS) return;
    uint32_t x0 = 0u, x1 = (uint32_t)j;
    tf2x32(k0, k1, x0, x1);
    uint32_t bits = x0 ^ x1;
    int f = j & 127;
    float v = fmaxf(fmaf(__ldg(S + j), g_scale[f], g_shift[f]), 0.f) * 2.0f;
    out[j] = (bits >> 31) ? v : 0.f;
}

// ---------------- driver -----------------------------------------------------
extern "C" void kernel_launch(void* const* d_in, const int* in_sizes, int n_in,
                              void* d_out, int out_size)
{
    const float* x   = (const float*)d_in[0];
    const int*   src = (const int*)d_in[1];
    const int*   dst = (const int*)d_in[2];
    const float* Ws0 = (const float*)d_in[3];
    const float* Wn0 = (const float*)d_in[4];
    const float* b0  = (const float*)d_in[5];
    const float* ga0 = (const float*)d_in[6];
    const float* be0 = (const float*)d_in[7];
    const float* Ws1 = (const float*)d_in[8];
    const float* Wn1 = (const float*)d_in[9];
    const float* b1  = (const float*)d_in[10];
    const float* ga1 = (const float*)d_in[11];
    const float* be1 = (const float*)d_in[12];
    const float* Ws2 = (const float*)d_in[13];
    const float* Wn2 = (const float*)d_in[14];
    const float* b2  = (const float*)d_in[15];
    float* out = (float*)d_out;

    // split(key(42)) under partitionable threefry (foldlike):
    //   dk_i = full output pair of threefry2x32((0,42), (0, i))
    uint32_t k00 = 0u, k01 = 0u; tf2x32(0u, 42u, k00, k01);   // dk0 = (k00, k01)
    uint32_t k10 = 0u, k11 = 1u; tf2x32(0u, 42u, k10, k11);   // dk1 = (k10, k11)

    float *pS, *pG, *pH;
    cudaGetSymbolAddress((void**)&pS, g_bufS);
    cudaGetSymbolAddress((void**)&pG, g_bufG);
    cudaGetSymbolAddress((void**)&pH, g_bufH);

    const int GEMM_GRID = (NNODES + 63) / 64;          // 1563
    const int AGG128_GRID = (NEDGES * 32 + 255) / 256; // 200000
    const int AGG64_GRID  = (NEDGES * 16 + 255) / 256; // 100000
    const int DROP_GRID = (NELEMS + 255) / 256;        // 50000

    // degree -> invdeg
    k_zero_deg<<<(NNODES + 255) / 256, 256>>>();
    k_count_deg<<<(NEDGES + 255) / 256, 256>>>(dst);
    k_finish_deg<<<(NNODES + 255) / 256, 256>>>();

    // ---- layer 0 ----
    sage_gemm<128, 8><<<GEMM_GRID, 256>>>(x, Wn0, nullptr, pG);
    sage_gemm<128, 8><<<GEMM_GRID, 256>>>(x, Ws0, b0, pS);
    k_edge_agg128<<<AGG128_GRID, 256>>>(pG, pS, src, dst);
    k_zero_stats<<<1, 128>>>();
    k_bn_stats<<<1024, 256>>>(pS);
    k_bn_finalize<<<1, 128>>>(ga0, be0);
    k_bn_relu_drop<<<DROP_GRID, 256>>>(pS, pH, k00, k01);

    // ---- layer 1 ----
    sage_gemm<128, 8><<<GEMM_GRID, 256>>>(pH, Wn1, nullptr, pG);
    sage_gemm<128, 8><<<GEMM_GRID, 256>>>(pH, Ws1, b1, pS);
    k_edge_agg128<<<AGG128_GRID, 256>>>(pG, pS, src, dst);
    k_zero_stats<<<1, 128>>>();
    k_bn_stats<<<1024, 256>>>(pS);
    k_bn_finalize<<<1, 128>>>(ga1, be1);
    k_bn_relu_drop<<<DROP_GRID, 256>>>(pS, pH, k10, k11);

    // ---- layer 2 (no BN / dropout), writes straight to d_out ----
    sage_gemm<64, 4><<<GEMM_GRID, 256>>>(pH, Wn2, nullptr, pG);
    sage_gemm<64, 4><<<GEMM_GRID, 256>>>(pH, Ws2, b2, out);
    k_edge_agg64<<<AGG64_GRID, 256>>>(pG, out, src, dst);
}

// round 3
// speedup vs baseline: 1.7254x; 1.7254x over previous
#include <cuda_runtime.h>
#include <cstdint>

#define NNODES 100000
#define NEDGES 1600000
#define NELEMS 12800000   // NNODES*128
#define SCAN_BLOCKS 391   // ceil(100000/256)

// ---------------- scratch (static device globals: allocation-free) ----------
__device__ float g_bufS[(size_t)NNODES * 128];   // self GEMM out / pre-activation accumulator
__device__ float g_bufG[(size_t)NNODES * 128];   // neigh GEMM out
__device__ float g_bufH[(size_t)NNODES * 128];   // hidden activations
__device__ float g_Wcat[128 * 256];              // concatenated [Ws|Wn]
__device__ int   g_degi[NNODES];
__device__ int   g_off[NNODES];
__device__ int   g_cursor[NNODES];
__device__ int   g_esrc[NEDGES];
__device__ int   g_bsum[512];
__device__ int   g_boff[512];
__device__ float g_sum[128];
__device__ float g_sumsq[128];
__device__ float g_scale[128];
__device__ float g_shift[128];

// ---------------- threefry2x32 (exact JAX implementation) -------------------
__host__ __device__ __forceinline__ void tf2x32(uint32_t k0, uint32_t k1,
                                                uint32_t& x0, uint32_t& x1)
{
    const uint32_t ks0 = k0, ks1 = k1, ks2 = k0 ^ k1 ^ 0x1BD11BDAu;
    const uint32_t ks[3] = {ks0, ks1, ks2};
    const int rot0[4] = {13, 15, 26, 6};
    const int rot1[4] = {17, 29, 16, 24};
    x0 += ks0; x1 += ks1;
#pragma unroll
    for (int b = 0; b < 5; b++) {
        const int* r = (b & 1) ? rot1 : rot0;
#pragma unroll
        for (int i = 0; i < 4; i++) {
            x0 += x1;
            x1 = (x1 << r[i]) | (x1 >> (32 - r[i]));
            x1 ^= x0;
        }
        x0 += ks[(b + 1) % 3];
        x1 += ks[(b + 2) % 3] + (uint32_t)(b + 1);
    }
}

// ---------------- CSR build --------------------------------------------------
__global__ void k_zero_deg()
{
    int i = blockIdx.x * blockDim.x + threadIdx.x;
    if (i < NNODES) g_degi[i] = 0;
}

__global__ void k_count_deg(const int* __restrict__ dst)
{
    int e = blockIdx.x * blockDim.x + threadIdx.x;
    if (e < NEDGES) atomicAdd(&g_degi[dst[e]], 1);
}

__global__ void k_scan1()
{
    __shared__ int sm[256];
    int b = blockIdx.x, t = threadIdx.x, i = b * 256 + t;
    int v = (i < NNODES) ? g_degi[i] : 0;
    sm[t] = v;
    __syncthreads();
#pragma unroll
    for (int d = 1; d < 256; d <<= 1) {
        int add = (t >= d) ? sm[t - d] : 0;
        __syncthreads();
        sm[t] += add;
        __syncthreads();
    }
    if (i < NNODES) g_off[i] = sm[t] - v;      // exclusive within block
    if (t == 255) g_bsum[b] = sm[255];
}

__global__ void k_scan2()
{
    __shared__ int sm[512];
    int t = threadIdx.x;
    int v = (t < SCAN_BLOCKS) ? g_bsum[t] : 0;
    sm[t] = v;
    __syncthreads();
#pragma unroll
    for (int d = 1; d < 512; d <<= 1) {
        int add = (t >= d) ? sm[t - d] : 0;
        __syncthreads();
        sm[t] += add;
        __syncthreads();
    }
    g_boff[t] = sm[t] - v;                     // exclusive block offsets
}

__global__ void k_scan3()
{
    int i = blockIdx.x * blockDim.x + threadIdx.x;
    if (i < NNODES) {
        int o = g_off[i] + g_boff[i >> 8];
        g_off[i] = o;
        g_cursor[i] = o;
    }
}

__global__ void k_scatter(const int* __restrict__ src, const int* __restrict__ dst)
{
    int e = blockIdx.x * blockDim.x + threadIdx.x;
    if (e < NEDGES) {
        int p = atomicAdd(&g_cursor[dst[e]], 1);
        g_esrc[p] = src[e];
    }
}

// ---------------- weight concat: Wc[k][0..F)=Ws[k], Wc[k][F..2F)=Wn[k] -------
__global__ void k_cat_w(const float* __restrict__ Ws, const float* __restrict__ Wn,
                        int F)
{
    int i = blockIdx.x * blockDim.x + threadIdx.x;
    if (i < 128 * F) {
        int k = i / F, c = i % F;
        g_Wcat[k * 2 * F + c]     = Ws[i];
        g_Wcat[k * 2 * F + F + c] = Wn[i];
    }
}

// ---------------- fused dual GEMM: [out1|out2] = H[N,128] @ Wc[128,FCAT] -----
// out1 gets bias. Row stride of out1/out2 = FCAT/2.
template <int FCAT>
__global__ void __launch_bounds__(256)
sage_gemm_dual(const float* __restrict__ H, const float* __restrict__ bias,
               float* __restrict__ out1, float* __restrict__ out2)
{
    constexpr int FH  = FCAT / 2;
    constexpr int CG  = FCAT / 4;     // float4 col groups (64 or 32)
    constexpr int TY  = 256 / CG;     // row groups (4 or 8)
    constexpr int RPT = 8;
    constexpr int BM  = TY * RPT;     // rows per block (32 or 64)
    __shared__ float hs[BM][128];

    const int t = threadIdx.x;
    const int row0 = blockIdx.x * BM;

    for (int i = t; i < BM * 32; i += 256) {
        int r = i >> 5, c = i & 31;
        int gr = row0 + r;
        float4 v = make_float4(0.f, 0.f, 0.f, 0.f);
        if (gr < NNODES) v = __ldg((const float4*)(H + (size_t)gr * 128) + c);
        *((float4*)&hs[r][0] + c) = v;
    }
    __syncthreads();

    const int tx = t % CG, ty = t / CG;
    float4 acc[RPT];
#pragma unroll
    for (int r = 0; r < RPT; r++) acc[r] = make_float4(0.f, 0.f, 0.f, 0.f);

    const float4* Wv = (const float4*)g_Wcat;
#pragma unroll 8
    for (int k = 0; k < 128; k += 4) {
        float4 b0 = __ldg(Wv + (k + 0) * CG + tx);
        float4 b1 = __ldg(Wv + (k + 1) * CG + tx);
        float4 b2 = __ldg(Wv + (k + 2) * CG + tx);
        float4 b3 = __ldg(Wv + (k + 3) * CG + tx);
#pragma unroll
        for (int r = 0; r < RPT; r++) {
            float4 a = *((const float4*)&hs[ty * RPT + r][k]);
            acc[r].x = fmaf(a.x, b0.x, fmaf(a.y, b1.x, fmaf(a.z, b2.x, fmaf(a.w, b3.x, acc[r].x))));
            acc[r].y = fmaf(a.x, b0.y, fmaf(a.y, b1.y, fmaf(a.z, b2.y, fmaf(a.w, b3.y, acc[r].y))));
            acc[r].z = fmaf(a.x, b0.z, fmaf(a.y, b1.z, fmaf(a.z, b2.z, fmaf(a.w, b3.z, acc[r].z))));
            acc[r].w = fmaf(a.x, b0.w, fmaf(a.y, b1.w, fmaf(a.z, b2.w, fmaf(a.w, b3.w, acc[r].w))));
        }
    }

    const bool first = (tx < CG / 2);
    float4 bb = make_float4(0.f, 0.f, 0.f, 0.f);
    if (first) bb = __ldg((const float4*)bias + tx);

#pragma unroll
    for (int r = 0; r < RPT; r++) {
        int gr = row0 + ty * RPT + r;
        if (gr >= NNODES) continue;
        if (first) {
            float4 o = make_float4(acc[r].x + bb.x, acc[r].y + bb.y,
                                   acc[r].z + bb.z, acc[r].w + bb.w);
            *((float4*)(out1 + (size_t)gr * FH) + tx) = o;
        } else {
            *((float4*)(out2 + (size_t)gr * FH) + (tx - CG / 2)) = acc[r];
        }
    }
}

// ---------------- CSR aggregation: S[n] += mean_{e in CSR(n)} G[src(e)] ------
__global__ void __launch_bounds__(256)
k_agg_csr128(const float* __restrict__ G, float* __restrict__ S)
{
    int gid = blockIdx.x * blockDim.x + threadIdx.x;
    int n = gid >> 5;
    if (n >= NNODES) return;
    int lane = threadIdx.x & 31;
    int cnt = g_degi[n];
    if (cnt == 0) return;
    int beg = g_off[n], end = beg + cnt;

    float4 acc0 = make_float4(0.f, 0.f, 0.f, 0.f);
    float4 acc1 = make_float4(0.f, 0.f, 0.f, 0.f);
    int i = beg;
    for (; i + 1 < end; i += 2) {
        int s0 = __ldg(&g_esrc[i]);
        int s1 = __ldg(&g_esrc[i + 1]);
        float4 v0 = __ldg((const float4*)(G + (size_t)s0 * 128) + lane);
        float4 v1 = __ldg((const float4*)(G + (size_t)s1 * 128) + lane);
        acc0.x += v0.x; acc0.y += v0.y; acc0.z += v0.z; acc0.w += v0.w;
        acc1.x += v1.x; acc1.y += v1.y; acc1.z += v1.z; acc1.w += v1.w;
    }
    if (i < end) {
        int s0 = __ldg(&g_esrc[i]);
        float4 v0 = __ldg((const float4*)(G + (size_t)s0 * 128) + lane);
        acc0.x += v0.x; acc0.y += v0.y; acc0.z += v0.z; acc0.w += v0.w;
    }
    float w = 1.0f / (float)cnt;
    float4* p = (float4*)(S + (size_t)n * 128) + lane;
    float4 cur = *p;
    cur.x = fmaf(acc0.x + acc1.x, w, cur.x);
    cur.y = fmaf(acc0.y + acc1.y, w, cur.y);
    cur.z = fmaf(acc0.z + acc1.z, w, cur.z);
    cur.w = fmaf(acc0.w + acc1.w, w, cur.w);
    *p = cur;
}

__global__ void __launch_bounds__(256)
k_agg_csr64(const float* __restrict__ G, float* __restrict__ S)
{
    int gid = blockIdx.x * blockDim.x + threadIdx.x;
    int n = gid >> 4;
    if (n >= NNODES) return;
    int lane = threadIdx.x & 15;
    int cnt = g_degi[n];
    if (cnt == 0) return;
    int beg = g_off[n], end = beg + cnt;

    float4 acc0 = make_float4(0.f, 0.f, 0.f, 0.f);
    float4 acc1 = make_float4(0.f, 0.f, 0.f, 0.f);
    int i = beg;
    for (; i + 1 < end; i += 2) {
        int s0 = __ldg(&g_esrc[i]);
        int s1 = __ldg(&g_esrc[i + 1]);
        float4 v0 = __ldg((const float4*)(G + (size_t)s0 * 64) + lane);
        float4 v1 = __ldg((const float4*)(G + (size_t)s1 * 64) + lane);
        acc0.x += v0.x; acc0.y += v0.y; acc0.z += v0.z; acc0.w += v0.w;
        acc1.x += v1.x; acc1.y += v1.y; acc1.z += v1.z; acc1.w += v1.w;
    }
    if (i < end) {
        int s0 = __ldg(&g_esrc[i]);
        float4 v0 = __ldg((const float4*)(G + (size_t)s0 * 64) + lane);
        acc0.x += v0.x; acc0.y += v0.y; acc0.z += v0.z; acc0.w += v0.w;
    }
    float w = 1.0f / (float)cnt;
    float4* p = (float4*)(S + (size_t)n * 64) + lane;
    float4 cur = *p;
    cur.x = fmaf(acc0.x + acc1.x, w, cur.x);
    cur.y = fmaf(acc0.y + acc1.y, w, cur.y);
    cur.z = fmaf(acc0.z + acc1.z, w, cur.z);
    cur.w = fmaf(acc0.w + acc1.w, w, cur.w);
    *p = cur;
}

// ---------------- batchnorm stats + finalize --------------------------------
__global__ void k_zero_stats()
{
    int t = threadIdx.x;
    if (t < 128) { g_sum[t] = 0.f; g_sumsq[t] = 0.f; }
}

__global__ void k_bn_stats(const float* __restrict__ S)
{
    int f = threadIdx.x & 127;
    int r = blockIdx.x * 2 + (threadIdx.x >> 7);
    int stride = gridDim.x * 2;
    float s = 0.f, q = 0.f;
    for (; r < NNODES; r += stride) {
        float v = S[(size_t)r * 128 + f];
        s += v;
        q = fmaf(v, v, q);
    }
    atomicAdd(&g_sum[f], s);
    atomicAdd(&g_sumsq[f], q);
}

__global__ void k_bn_finalize(const float* __restrict__ gamma, const float* __restrict__ beta)
{
    int f = threadIdx.x;
    float mu = g_sum[f] * (1.0f / NNODES);
    float var = fmaxf(g_sumsq[f] * (1.0f / NNODES) - mu * mu, 0.f);
    float sc = gamma[f] * rsqrtf(var + 1e-5f);
    g_scale[f] = sc;
    g_shift[f] = beta[f] - mu * sc;
}

// ---------------- fused BN * ReLU * dropout (JAX partitionable threefry) ----
__global__ void k_bn_relu_drop(const float* __restrict__ S, float* __restrict__ out,
                               uint32_t k0, uint32_t k1)
{
    int j = blockIdx.x * blockDim.x + threadIdx.x;
    if (j >= NELEMS) return;
    uint32_t x0 = 0u, x1 = (uint32_t)j;
    tf2x32(k0, k1, x0, x1);
    uint32_t bits = x0 ^ x1;
    int f = j & 127;
    float v = fmaxf(fmaf(__ldg(S + j), g_scale[f], g_shift[f]), 0.f) * 2.0f;
    out[j] = (bits >> 31) ? v : 0.f;
}

// ---------------- driver -----------------------------------------------------
extern "C" void kernel_launch(void* const* d_in, const int* in_sizes, int n_in,
                              void* d_out, int out_size)
{
    const float* x   = (const float*)d_in[0];
    const int*   src = (const int*)d_in[1];
    const int*   dst = (const int*)d_in[2];
    const float* Ws0 = (const float*)d_in[3];
    const float* Wn0 = (const float*)d_in[4];
    const float* b0  = (const float*)d_in[5];
    const float* ga0 = (const float*)d_in[6];
    const float* be0 = (const float*)d_in[7];
    const float* Ws1 = (const float*)d_in[8];
    const float* Wn1 = (const float*)d_in[9];
    const float* b1  = (const float*)d_in[10];
    const float* ga1 = (const float*)d_in[11];
    const float* be1 = (const float*)d_in[12];
    const float* Ws2 = (const float*)d_in[13];
    const float* Wn2 = (const float*)d_in[14];
    const float* b2  = (const float*)d_in[15];
    float* out = (float*)d_out;

    // dropout keys (partitionable threefry, foldlike split)
    uint32_t k00 = 0u, k01 = 0u; tf2x32(0u, 42u, k00, k01);   // dk0
    uint32_t k10 = 0u, k11 = 1u; tf2x32(0u, 42u, k10, k11);   // dk1

    float *pS, *pG, *pH;
    cudaGetSymbolAddress((void**)&pS, g_bufS);
    cudaGetSymbolAddress((void**)&pG, g_bufG);
    cudaGetSymbolAddress((void**)&pH, g_bufH);

    const int GRID_N256  = (NNODES + 255) / 256;
    const int GRID_E256  = (NEDGES + 255) / 256;
    const int GEMM_GRID256 = (NNODES + 31) / 32;   // BM=32, FCAT=256
    const int GEMM_GRID128 = (NNODES + 63) / 64;   // BM=64, FCAT=128
    const int AGG128_GRID = (NNODES * 32 + 255) / 256;
    const int AGG64_GRID  = (NNODES * 16 + 255) / 256;
    const int DROP_GRID = (NELEMS + 255) / 256;

    // ---- CSR build (once, reused by all 3 aggregations) ----
    k_zero_deg<<<GRID_N256, 256>>>();
    k_count_deg<<<GRID_E256, 256>>>(dst);
    k_scan1<<<SCAN_BLOCKS, 256>>>();
    k_scan2<<<1, 512>>>();
    k_scan3<<<SCAN_BLOCKS, 256>>>();
    k_scatter<<<GRID_E256, 256>>>(src, dst);

    // ---- layer 0 ----
    k_cat_w<<<(128 * 128 + 255) / 256, 256>>>(Ws0, Wn0, 128);
    sage_gemm_dual<256><<<GEMM_GRID256, 256>>>(x, b0, pS, pG);
    k_agg_csr128<<<AGG128_GRID, 256>>>(pG, pS);
    k_zero_stats<<<1, 128>>>();
    k_bn_stats<<<1024, 256>>>(pS);
    k_bn_finalize<<<1, 128>>>(ga0, be0);
    k_bn_relu_drop<<<DROP_GRID, 256>>>(pS, pH, k00, k01);

    // ---- layer 1 ----
    k_cat_w<<<(128 * 128 + 255) / 256, 256>>>(Ws1, Wn1, 128);
    sage_gemm_dual<256><<<GEMM_GRID256, 256>>>(pH, b1, pS, pG);
    k_agg_csr128<<<AGG128_GRID, 256>>>(pG, pS);
    k_zero_stats<<<1, 128>>>();
    k_bn_stats<<<1024, 256>>>(pS);
    k_bn_finalize<<<1, 128>>>(ga1, be1);
    k_bn_relu_drop<<<DROP_GRID, 256>>>(pS, pH, k10, k11);

    // ---- layer 2 (no BN / dropout), self-part straight to d_out ----
    k_cat_w<<<(128 * 64 + 255) / 256, 256>>>(Ws2, Wn2, 64);
    sage_gemm_dual<128><<<GEMM_GRID128, 256>>>(pH, b2, out, pG);
    k_agg_csr64<<<AGG64_GRID, 256>>>(pG, out);
}

// round 4
// speedup vs baseline: 2.0120x; 1.1661x over previous
#include <cuda_runtime.h>
#include <cuda_bf16.h>
#include <cstdint>

#define NNODES 100000
#define NEDGES 1600000
#define NELEMS 12800000   // NNODES*128
#define SCAN_BLOCKS 391   // ceil(100000/256)

// ---------------- scratch (static device globals: allocation-free) ----------
__device__ float g_bufS[(size_t)NNODES * 128];   // self GEMM out / accumulator
__device__ float g_bufG[(size_t)NNODES * 128];   // neigh GEMM out
__device__ __align__(16) __nv_bfloat16 g_Ahi[(size_t)NNODES * 128];
__device__ __align__(16) __nv_bfloat16 g_Alo[(size_t)NNODES * 128];
__device__ __align__(16) __nv_bfloat16 g_BtHi[256 * 128];   // [FCAT][128] n-major
__device__ __align__(16) __nv_bfloat16 g_BtLo[256 * 128];
__device__ int   g_degi[NNODES];
__device__ int   g_off[NNODES];
__device__ int   g_cursor[NNODES];
__device__ int   g_esrc[NEDGES];
__device__ int   g_bsum[512];
__device__ int   g_boff[512];
__device__ float g_sum[128];
__device__ float g_sumsq[128];
__device__ float g_scale[128];
__device__ float g_shift[128];

// ---------------- threefry2x32 (exact JAX implementation) -------------------
__host__ __device__ __forceinline__ void tf2x32(uint32_t k0, uint32_t k1,
                                                uint32_t& x0, uint32_t& x1)
{
    const uint32_t ks0 = k0, ks1 = k1, ks2 = k0 ^ k1 ^ 0x1BD11BDAu;
    const uint32_t ks[3] = {ks0, ks1, ks2};
    const int rot0[4] = {13, 15, 26, 6};
    const int rot1[4] = {17, 29, 16, 24};
    x0 += ks0; x1 += ks1;
#pragma unroll
    for (int b = 0; b < 5; b++) {
        const int* r = (b & 1) ? rot1 : rot0;
#pragma unroll
        for (int i = 0; i < 4; i++) {
            x0 += x1;
            x1 = (x1 << r[i]) | (x1 >> (32 - r[i]));
            x1 ^= x0;
        }
        x0 += ks[(b + 1) % 3];
        x1 += ks[(b + 2) % 3] + (uint32_t)(b + 1);
    }
}

// ---------------- CSR build --------------------------------------------------
__global__ void k_zero_deg()
{
    int i = blockIdx.x * blockDim.x + threadIdx.x;
    if (i < NNODES) g_degi[i] = 0;
}

__global__ void k_count_deg(const int* __restrict__ dst)
{
    int e = blockIdx.x * blockDim.x + threadIdx.x;
    if (e < NEDGES) atomicAdd(&g_degi[dst[e]], 1);
}

__global__ void k_scan1()
{
    __shared__ int sm[256];
    int b = blockIdx.x, t = threadIdx.x, i = b * 256 + t;
    int v = (i < NNODES) ? g_degi[i] : 0;
    sm[t] = v;
    __syncthreads();
#pragma unroll
    for (int d = 1; d < 256; d <<= 1) {
        int add = (t >= d) ? sm[t - d] : 0;
        __syncthreads();
        sm[t] += add;
        __syncthreads();
    }
    if (i < NNODES) g_off[i] = sm[t] - v;
    if (t == 255) g_bsum[b] = sm[255];
}

__global__ void k_scan2()
{
    __shared__ int sm[512];
    int t = threadIdx.x;
    int v = (t < SCAN_BLOCKS) ? g_bsum[t] : 0;
    sm[t] = v;
    __syncthreads();
#pragma unroll
    for (int d = 1; d < 512; d <<= 1) {
        int add = (t >= d) ? sm[t - d] : 0;
        __syncthreads();
        sm[t] += add;
        __syncthreads();
    }
    g_boff[t] = sm[t] - v;
}

__global__ void k_scan3()
{
    int i = blockIdx.x * blockDim.x + threadIdx.x;
    if (i < NNODES) {
        int o = g_off[i] + g_boff[i >> 8];
        g_off[i] = o;
        g_cursor[i] = o;
    }
}

__global__ void k_scatter(const int* __restrict__ src, const int* __restrict__ dst)
{
    int e = blockIdx.x * blockDim.x + threadIdx.x;
    if (e < NEDGES) {
        int p = atomicAdd(&g_cursor[dst[e]], 1);
        g_esrc[p] = src[e];
    }
}

// ---------------- weight concat -> transposed bf16 hi/lo --------------------
// Bt[c][k] = (c<F ? Ws[k][c] : Wn[k][c-F]), split into bf16 hi + lo.
__global__ void k_cat_w_bf16(const float* __restrict__ Ws, const float* __restrict__ Wn,
                             int F)
{
    int i = blockIdx.x * blockDim.x + threadIdx.x;
    if (i >= 2 * F * 128) return;
    int c = i >> 7, k = i & 127;
    float w = (c < F) ? __ldg(&Ws[k * F + c]) : __ldg(&Wn[k * F + (c - F)]);
    __nv_bfloat16 hi = __float2bfloat16_rn(w);
    g_BtHi[c * 128 + k] = hi;
    g_BtLo[c * 128 + k] = __float2bfloat16_rn(w - __bfloat162float(hi));
}

// ---------------- convert x -> bf16 hi/lo ------------------------------------
__global__ void k_cvt_x(const float* __restrict__ x)
{
    int j2 = blockIdx.x * blockDim.x + threadIdx.x;
    if (j2 >= NELEMS / 2) return;
    float2 v = __ldg((const float2*)x + j2);
    __nv_bfloat16 h0 = __float2bfloat16_rn(v.x);
    __nv_bfloat16 h1 = __float2bfloat16_rn(v.y);
    __nv_bfloat16 l0 = __float2bfloat16_rn(v.x - __bfloat162float(h0));
    __nv_bfloat16 l1 = __float2bfloat16_rn(v.y - __bfloat162float(h1));
    ((__nv_bfloat162*)g_Ahi)[j2] = __nv_bfloat162(h0, h1);
    ((__nv_bfloat162*)g_Alo)[j2] = __nv_bfloat162(l0, l1);
}

// ---------------- tensor-core GEMM (bf16x3 split, fp32 accumulate) ----------
__device__ __forceinline__ void ldsm_x4(uint32_t (&r)[4], uint32_t addr)
{
    asm volatile("ldmatrix.sync.aligned.m8n8.x4.shared.b16 {%0,%1,%2,%3}, [%4];\n"
                 : "=r"(r[0]), "=r"(r[1]), "=r"(r[2]), "=r"(r[3]) : "r"(addr));
}

__device__ __forceinline__ void mma_bf16(float (&d)[4], const uint32_t (&a)[4],
                                         uint32_t b0, uint32_t b1)
{
    asm volatile("mma.sync.aligned.m16n8k16.row.col.f32.bf16.bf16.f32 "
                 "{%0,%1,%2,%3}, {%4,%5,%6,%7}, {%8,%9}, {%0,%1,%2,%3};\n"
                 : "+f"(d[0]), "+f"(d[1]), "+f"(d[2]), "+f"(d[3])
                 : "r"(a[0]), "r"(a[1]), "r"(a[2]), "r"(a[3]), "r"(b0), "r"(b1));
}

// C[N, FCAT] = A[N,128] @ Bt^T, A = Ahi+Alo, B = Bhi+Blo (bf16x3).
// Block: 128 rows x 64 cols, 8 warps (4m x 2n), K=128 staged fully in smem.
// Row pad 8 elems (272B stride) -> conflict-free ldmatrix.
template <int FCAT>
__global__ void __launch_bounds__(256)
gemm_bf16x3(const __nv_bfloat16* __restrict__ Ahi, const __nv_bfloat16* __restrict__ Alo,
            const float* __restrict__ bias, float* __restrict__ out1, float* __restrict__ out2)
{
    constexpr int FH = FCAT / 2;
    extern __shared__ char sm[];
    // offsets: AsHi 0 (34816), AsLo 34816, BsHi 69632 (17408), BsLo 87040
    const int tid = threadIdx.x;
    const int row0 = blockIdx.x * 128;
    const int col0 = blockIdx.y * 64;

    // stage A (128x128 hi+lo) and B (64x128 hi+lo)
    {
        const uint4* gAhi = (const uint4*)Ahi;
        const uint4* gAlo = (const uint4*)Alo;
        for (int idx = tid; idx < 2048; idx += 256) {
            int r = idx >> 4, c = idx & 15;
            int gr = row0 + r;
            uint4 vh = make_uint4(0u, 0u, 0u, 0u), vl = vh;
            if (gr < NNODES) {
                vh = __ldg(gAhi + (size_t)gr * 16 + c);
                vl = __ldg(gAlo + (size_t)gr * 16 + c);
            }
            *(uint4*)(sm + r * 272 + c * 16) = vh;
            *(uint4*)(sm + 34816 + r * 272 + c * 16) = vl;
        }
        const uint4* gBh = (const uint4*)g_BtHi;
        const uint4* gBl = (const uint4*)g_BtLo;
        for (int idx = tid; idx < 1024; idx += 256) {
            int r = idx >> 4, c = idx & 15;
            *(uint4*)(sm + 69632 + r * 272 + c * 16) = __ldg(gBh + (size_t)(col0 + r) * 16 + c);
            *(uint4*)(sm + 87040 + r * 272 + c * 16) = __ldg(gBl + (size_t)(col0 + r) * 16 + c);
        }
    }
    __syncthreads();

    const int lane = tid & 31, wid = tid >> 5;
    const int m_base = (wid & 3) * 32, n_base = (wid >> 2) * 32;
    const int g = lane >> 3, rr = lane & 7;

    uint32_t smb = (uint32_t)__cvta_generic_to_shared(sm);
    const uint32_t sA_hi = smb, sA_lo = smb + 34816, sB_hi = smb + 69632, sB_lo = smb + 87040;

    uint32_t aoff[2], boff[2];
#pragma unroll
    for (int mt = 0; mt < 2; mt++) {
        int arow = m_base + mt * 16 + (g & 1) * 8 + rr;
        aoff[mt] = (uint32_t)(arow * 272 + (g >> 1) * 16);
    }
#pragma unroll
    for (int ng = 0; ng < 2; ng++) {
        int brow = n_base + ng * 16 + (g >> 1) * 8 + rr;
        boff[ng] = (uint32_t)(brow * 272 + (g & 1) * 16);
    }

    float acc[2][4][4];
#pragma unroll
    for (int mt = 0; mt < 2; mt++)
#pragma unroll
        for (int j = 0; j < 4; j++)
#pragma unroll
            for (int q = 0; q < 4; q++) acc[mt][j][q] = 0.f;

#pragma unroll
    for (int ks = 0; ks < 8; ks++) {
        const uint32_t kb = ks * 32;
        uint32_t ah[2][4], al[2][4], bh[2][4], bl[2][4];
        ldsm_x4(ah[0], sA_hi + aoff[0] + kb);
        ldsm_x4(ah[1], sA_hi + aoff[1] + kb);
        ldsm_x4(al[0], sA_lo + aoff[0] + kb);
        ldsm_x4(al[1], sA_lo + aoff[1] + kb);
        ldsm_x4(bh[0], sB_hi + boff[0] + kb);
        ldsm_x4(bh[1], sB_hi + boff[1] + kb);
        ldsm_x4(bl[0], sB_lo + boff[0] + kb);
        ldsm_x4(bl[1], sB_lo + boff[1] + kb);
#pragma unroll
        for (int mt = 0; mt < 2; mt++) {
#pragma unroll
            for (int j = 0; j < 4; j++) {
                const int ng = j >> 1, s = (j & 1) * 2;
                mma_bf16(acc[mt][j], ah[mt], bh[ng][s], bh[ng][s + 1]);
                mma_bf16(acc[mt][j], ah[mt], bl[ng][s], bl[ng][s + 1]);
                mma_bf16(acc[mt][j], al[mt], bh[ng][s], bh[ng][s + 1]);
            }
        }
    }

    // store: block col range is entirely within out1 or out2
    const bool sel = (col0 < FH);
    float* outp = sel ? out1 : out2;
    const int cbase = col0 - (sel ? 0 : FH);
    const int tr = lane >> 2, tc = (lane & 3) * 2;

#pragma unroll
    for (int j = 0; j < 4; j++) {
        int gc = cbase + n_base + j * 8 + tc;
        float bx = 0.f, by = 0.f;
        if (sel) { bx = __ldg(bias + gc); by = __ldg(bias + gc + 1); }
#pragma unroll
        for (int mt = 0; mt < 2; mt++) {
            int r0g = row0 + m_base + mt * 16 + tr;
            if (r0g < NNODES) {
                float2 v = make_float2(acc[mt][j][0] + bx, acc[mt][j][1] + by);
                *(float2*)(outp + (size_t)r0g * FH + gc) = v;
            }
            int r1g = r0g + 8;
            if (r1g < NNODES) {
                float2 v = make_float2(acc[mt][j][2] + bx, acc[mt][j][3] + by);
                *(float2*)(outp + (size_t)r1g * FH + gc) = v;
            }
        }
    }
}

// ---------------- CSR aggregation --------------------------------------------
__global__ void __launch_bounds__(256)
k_agg_csr128(const float* __restrict__ G, float* __restrict__ S)
{
    int gid = blockIdx.x * blockDim.x + threadIdx.x;
    int n = gid >> 5;
    if (n >= NNODES) return;
    int lane = threadIdx.x & 31;
    int cnt = g_degi[n];
    if (cnt == 0) return;
    int beg = g_off[n], end = beg + cnt;

    float4 acc0 = make_float4(0.f, 0.f, 0.f, 0.f);
    float4 acc1 = make_float4(0.f, 0.f, 0.f, 0.f);
    int i = beg;
    for (; i + 1 < end; i += 2) {
        int s0 = __ldg(&g_esrc[i]);
        int s1 = __ldg(&g_esrc[i + 1]);
        float4 v0 = __ldg((const float4*)(G + (size_t)s0 * 128) + lane);
        float4 v1 = __ldg((const float4*)(G + (size_t)s1 * 128) + lane);
        acc0.x += v0.x; acc0.y += v0.y; acc0.z += v0.z; acc0.w += v0.w;
        acc1.x += v1.x; acc1.y += v1.y; acc1.z += v1.z; acc1.w += v1.w;
    }
    if (i < end) {
        int s0 = __ldg(&g_esrc[i]);
        float4 v0 = __ldg((const float4*)(G + (size_t)s0 * 128) + lane);
        acc0.x += v0.x; acc0.y += v0.y; acc0.z += v0.z; acc0.w += v0.w;
    }
    float w = 1.0f / (float)cnt;
    float4* p = (float4*)(S + (size_t)n * 128) + lane;
    float4 cur = *p;
    cur.x = fmaf(acc0.x + acc1.x, w, cur.x);
    cur.y = fmaf(acc0.y + acc1.y, w, cur.y);
    cur.z = fmaf(acc0.z + acc1.z, w, cur.z);
    cur.w = fmaf(acc0.w + acc1.w, w, cur.w);
    *p = cur;
}

__global__ void __launch_bounds__(256)
k_agg_csr64(const float* __restrict__ G, float* __restrict__ S)
{
    int gid = blockIdx.x * blockDim.x + threadIdx.x;
    int n = gid >> 4;
    if (n >= NNODES) return;
    int lane = threadIdx.x & 15;
    int cnt = g_degi[n];
    if (cnt == 0) return;
    int beg = g_off[n], end = beg + cnt;

    float4 acc0 = make_float4(0.f, 0.f, 0.f, 0.f);
    float4 acc1 = make_float4(0.f, 0.f, 0.f, 0.f);
    int i = beg;
    for (; i + 1 < end; i += 2) {
        int s0 = __ldg(&g_esrc[i]);
        int s1 = __ldg(&g_esrc[i + 1]);
        float4 v0 = __ldg((const float4*)(G + (size_t)s0 * 64) + lane);
        float4 v1 = __ldg((const float4*)(G + (size_t)s1 * 64) + lane);
        acc0.x += v0.x; acc0.y += v0.y; acc0.z += v0.z; acc0.w += v0.w;
        acc1.x += v1.x; acc1.y += v1.y; acc1.z += v1.z; acc1.w += v1.w;
    }
    if (i < end) {
        int s0 = __ldg(&g_esrc[i]);
        float4 v0 = __ldg((const float4*)(G + (size_t)s0 * 64) + lane);
        acc0.x += v0.x; acc0.y += v0.y; acc0.z += v0.z; acc0.w += v0.w;
    }
    float w = 1.0f / (float)cnt;
    float4* p = (float4*)(S + (size_t)n * 64) + lane;
    float4 cur = *p;
    cur.x = fmaf(acc0.x + acc1.x, w, cur.x);
    cur.y = fmaf(acc0.y + acc1.y, w, cur.y);
    cur.z = fmaf(acc0.z + acc1.z, w, cur.z);
    cur.w = fmaf(acc0.w + acc1.w, w, cur.w);
    *p = cur;
}

// ---------------- batchnorm stats + finalize --------------------------------
__global__ void k_zero_stats()
{
    int t = threadIdx.x;
    if (t < 128) { g_sum[t] = 0.f; g_sumsq[t] = 0.f; }
}

__global__ void k_bn_stats(const float* __restrict__ S)
{
    int f = threadIdx.x & 127;
    int r = blockIdx.x * 2 + (threadIdx.x >> 7);
    int stride = gridDim.x * 2;
    float s = 0.f, q = 0.f;
    for (; r < NNODES; r += stride) {
        float v = S[(size_t)r * 128 + f];
        s += v;
        q = fmaf(v, v, q);
    }
    atomicAdd(&g_sum[f], s);
    atomicAdd(&g_sumsq[f], q);
}

__global__ void k_bn_finalize(const float* __restrict__ gamma, const float* __restrict__ beta)
{
    int f = threadIdx.x;
    float mu = g_sum[f] * (1.0f / NNODES);
    float var = fmaxf(g_sumsq[f] * (1.0f / NNODES) - mu * mu, 0.f);
    float sc = gamma[f] * rsqrtf(var + 1e-5f);
    g_scale[f] = sc;
    g_shift[f] = beta[f] - mu * sc;
}

// ---------------- fused BN * ReLU * dropout -> bf16 hi/lo ---------------------
__global__ void k_bn_relu_drop(const float* __restrict__ S,
                               uint32_t k0, uint32_t k1)
{
    int j2 = blockIdx.x * blockDim.x + threadIdx.x;
    if (j2 >= NELEMS / 2) return;
    int j = j2 * 2;
    uint32_t x0 = 0u, x1 = (uint32_t)j;
    tf2x32(k0, k1, x0, x1);
    uint32_t y0 = 0u, y1 = (uint32_t)(j + 1);
    tf2x32(k0, k1, y0, y1);
    int f = j & 127;
    float2 s = __ldg((const float2*)S + j2);
    float v0 = fmaxf(fmaf(s.x, g_scale[f], g_shift[f]), 0.f) * 2.0f;
    float v1 = fmaxf(fmaf(s.y, g_scale[f + 1], g_shift[f + 1]), 0.f) * 2.0f;
    v0 = ((x0 ^ x1) >> 31) ? v0 : 0.f;
    v1 = ((y0 ^ y1) >> 31) ? v1 : 0.f;
    __nv_bfloat16 h0 = __float2bfloat16_rn(v0);
    __nv_bfloat16 h1 = __float2bfloat16_rn(v1);
    __nv_bfloat16 l0 = __float2bfloat16_rn(v0 - __bfloat162float(h0));
    __nv_bfloat16 l1 = __float2bfloat16_rn(v1 - __bfloat162float(h1));
    ((__nv_bfloat162*)g_Ahi)[j2] = __nv_bfloat162(h0, h1);
    ((__nv_bfloat162*)g_Alo)[j2] = __nv_bfloat162(l0, l1);
}

// ---------------- driver -----------------------------------------------------
extern "C" void kernel_launch(void* const* d_in, const int* in_sizes, int n_in,
                              void* d_out, int out_size)
{
    const float* x   = (const float*)d_in[0];
    const int*   src = (const int*)d_in[1];
    const int*   dst = (const int*)d_in[2];
    const float* Ws0 = (const float*)d_in[3];
    const float* Wn0 = (const float*)d_in[4];
    const float* b0  = (const float*)d_in[5];
    const float* ga0 = (const float*)d_in[6];
    const float* be0 = (const float*)d_in[7];
    const float* Ws1 = (const float*)d_in[8];
    const float* Wn1 = (const float*)d_in[9];
    const float* b1  = (const float*)d_in[10];
    const float* ga1 = (const float*)d_in[11];
    const float* be1 = (const float*)d_in[12];
    const float* Ws2 = (const float*)d_in[13];
    const float* Wn2 = (const float*)d_in[14];
    const float* b2  = (const float*)d_in[15];
    float* out = (float*)d_out;

    // dropout keys (partitionable threefry, foldlike split)
    uint32_t k00 = 0u, k01 = 0u; tf2x32(0u, 42u, k00, k01);
    uint32_t k10 = 0u, k11 = 1u; tf2x32(0u, 42u, k10, k11);

    float *pS, *pG;
    __nv_bfloat16 *pAhi, *pAlo;
    cudaGetSymbolAddress((void**)&pS, g_bufS);
    cudaGetSymbolAddress((void**)&pG, g_bufG);
    cudaGetSymbolAddress((void**)&pAhi, g_Ahi);
    cudaGetSymbolAddress((void**)&pAlo, g_Alo);

    const int SMEM = 104448;
    cudaFuncSetAttribute(gemm_bf16x3<256>, cudaFuncAttributeMaxDynamicSharedMemorySize, SMEM);
    cudaFuncSetAttribute(gemm_bf16x3<128>, cudaFuncAttributeMaxDynamicSharedMemorySize, SMEM);

    const int GRID_N256 = (NNODES + 255) / 256;
    const int GRID_E256 = (NEDGES + 255) / 256;
    const dim3 GG256((NNODES + 127) / 128, 4);
    const dim3 GG128((NNODES + 127) / 128, 2);
    const int AGG128_GRID = (NNODES * 32 + 255) / 256;
    const int AGG64_GRID  = (NNODES * 16 + 255) / 256;
    const int DROP_GRID = (NELEMS / 2 + 255) / 256;

    // ---- CSR build (once) ----
    k_zero_deg<<<GRID_N256, 256>>>();
    k_count_deg<<<GRID_E256, 256>>>(dst);
    k_scan1<<<SCAN_BLOCKS, 256>>>();
    k_scan2<<<1, 512>>>();
    k_scan3<<<SCAN_BLOCKS, 256>>>();
    k_scatter<<<GRID_E256, 256>>>(src, dst);

    // ---- layer 0 ----
    k_cvt_x<<<DROP_GRID, 256>>>(x);
    k_cat_w_bf16<<<(256 * 128 + 255) / 256, 256>>>(Ws0, Wn0, 128);
    gemm_bf16x3<256><<<GG256, 256, SMEM>>>(pAhi, pAlo, b0, pS, pG);
    k_agg_csr128<<<AGG128_GRID, 256>>>(pG, pS);
    k_zero_stats<<<1, 128>>>();
    k_bn_stats<<<1024, 256>>>(pS);
    k_bn_finalize<<<1, 128>>>(ga0, be0);
    k_bn_relu_drop<<<DROP_GRID, 256>>>(pS, k00, k01);

    // ---- layer 1 ----
    k_cat_w_bf16<<<(256 * 128 + 255) / 256, 256>>>(Ws1, Wn1, 128);
    gemm_bf16x3<256><<<GG256, 256, SMEM>>>(pAhi, pAlo, b1, pS, pG);
    k_agg_csr128<<<AGG128_GRID, 256>>>(pG, pS);
    k_zero_stats<<<1, 128>>>();
    k_bn_stats<<<1024, 256>>>(pS);
    k_bn_finalize<<<1, 128>>>(ga1, be1);
    k_bn_relu_drop<<<DROP_GRID, 256>>>(pS, k10, k11);

    // ---- layer 2 (no BN / dropout), self-part straight to d_out ----
    k_cat_w_bf16<<<(128 * 128 + 255) / 256, 256>>>(Ws2, Wn2, 64);
    gemm_bf16x3<128><<<GG128, 256, SMEM>>>(pAhi, pAlo, b2, out, pG);
    k_agg_csr64<<<AGG64_GRID, 256>>>(pG, out);
}